// round 12
// baseline (speedup 1.0000x reference)
#include <cuda_runtime.h>
#include <cstdint>

#define NB 32
#define TT 2048
#define II 512
#define HH 1024

// =====================================================================
// Phase 1: proj = x @ w_ih^T + b_ih  -> second half of d_out (scratch).
// =====================================================================
__global__ __launch_bounds__(256) void proj_gemm(
    const float* __restrict__ x,
    const float* __restrict__ wih,
    const float* __restrict__ bih,
    float* __restrict__ proj)
{
    __shared__ float As[16][132];
    __shared__ float Bs[16][68];

    const int tid = threadIdx.x;
    const int n0 = blockIdx.x * 64;
    const int m0 = blockIdx.y * 128;

    const int ar = tid >> 2;
    const int ac = (tid & 3) << 2;
    const int ty = tid >> 4;
    const int tx = tid & 15;

    float acc[8][4];
#pragma unroll
    for (int i = 0; i < 8; i++)
#pragma unroll
        for (int j = 0; j < 4; j++) acc[i][j] = 0.0f;

    for (int kk = 0; kk < II / 16; kk++) {
        const int k0 = kk * 16;
        const float4 a0 = *reinterpret_cast<const float4*>(
            &x[(size_t)(m0 + ar) * II + k0 + ac]);
        const float4 a1 = *reinterpret_cast<const float4*>(
            &x[(size_t)(m0 + 64 + ar) * II + k0 + ac]);
        const float4 b0 = *reinterpret_cast<const float4*>(
            &wih[(size_t)(n0 + ar) * II + k0 + ac]);

        __syncthreads();
        As[ac + 0][ar] = a0.x;  As[ac + 1][ar] = a0.y;
        As[ac + 2][ar] = a0.z;  As[ac + 3][ar] = a0.w;
        As[ac + 0][64 + ar] = a1.x;  As[ac + 1][64 + ar] = a1.y;
        As[ac + 2][64 + ar] = a1.z;  As[ac + 3][64 + ar] = a1.w;
        Bs[ac + 0][ar] = b0.x;  Bs[ac + 1][ar] = b0.y;
        Bs[ac + 2][ar] = b0.z;  Bs[ac + 3][ar] = b0.w;
        __syncthreads();

#pragma unroll
        for (int k = 0; k < 16; k++) {
            const float4 av0 = *reinterpret_cast<const float4*>(&As[k][ty * 8]);
            const float4 av1 = *reinterpret_cast<const float4*>(&As[k][ty * 8 + 4]);
            const float4 bv  = *reinterpret_cast<const float4*>(&Bs[k][tx * 4]);
            float a[8] = {av0.x, av0.y, av0.z, av0.w, av1.x, av1.y, av1.z, av1.w};
            float b[4] = {bv.x, bv.y, bv.z, bv.w};
#pragma unroll
            for (int i = 0; i < 8; i++)
#pragma unroll
                for (int j = 0; j < 4; j++)
                    acc[i][j] += a[i] * b[j];
        }
    }

    const float4 bias = *reinterpret_cast<const float4*>(&bih[n0 + tx * 4]);
#pragma unroll
    for (int r = 0; r < 8; r++) {
        const int m = m0 + ty * 8 + r;
        float4 o;
        o.x = acc[r][0] + bias.x;
        o.y = acc[r][1] + bias.y;
        o.z = acc[r][2] + bias.z;
        o.w = acc[r][3] + bias.w;
        *reinterpret_cast<float4*>(&proj[(size_t)m * HH + n0 + tx * 4]) = o;
    }
}

// =====================================================================
// Phase 2: persistent recurrence.  h_t = h_{t-1} @ W^T + proj[:, t-1]
// 1024 threads, 32 warps; warp w owns a 32-wide k slice; lane = n.
// FFMA2 accumulators (4 x b64 = 8 j-columns). h transposed ([k][n]) in
// ping-pong L2 scratch (__ldcg/__stcg: L1 not coherent across SMs).
// Two-stage smem reduce (32 -> 4 -> 1 slices), rotated columns =
// conflict-free. Hierarchical grid barrier: 16 group counters (8 CTAs)
// -> 1 global counter (16 arrivals) -> phase flip.
// smem: Wp 32KB + partial 32KB + partial2 4KB = 68KB (1 CTA/SM).
// =====================================================================
#define RBLOCKS 128

__device__ float g_ht[2][HH * 32];      // 256 KB transposed h ping-pong
__device__ unsigned g_gcnt[16];
__device__ unsigned g_count2 = 0;
__device__ unsigned g_phase = 0;

__device__ __forceinline__ void grid_barrier(int tid)
{
    __syncthreads();
    if (tid == 0) {
        volatile unsigned* vphase = &g_phase;
        const unsigned my = *vphase;      // read BEFORE arriving
        __threadfence();                  // publish writes (L2)
        const unsigned g = blockIdx.x >> 3;   // 16 groups of 8 CTAs
        if (atomicAdd(&g_gcnt[g], 1u) == 7) {
            g_gcnt[g] = 0;                // safe: no arrivals until after release
            __threadfence();
            if (atomicAdd(&g_count2, 1u) == 15) {
                g_count2 = 0;
                __threadfence();
                *vphase = my + 1;         // release
            }
        }
        while (*vphase == my) { }
        __threadfence();                  // acquire
    }
    __syncthreads();
}

__global__ __launch_bounds__(1024) void recurrence(
    const float* __restrict__ whh,
    const float* __restrict__ proj,
    float* __restrict__ out)
{
    __shared__ float4 Wp[HH * 2];            // [k]{j0..3},{j4..7}  32 KB
    __shared__ float  partial[32][8][32];    // [slice][j][rot(n)]  32 KB
    __shared__ float  partial2[4][8][32];    // [q][j][rot(n)]       4 KB

    const int tid  = threadIdx.x;
    const int w    = tid >> 5;     // warp 0..31 -> 32-wide k slice
    const int lane = tid & 31;     // lane = n
    const int j0   = blockIdx.x * 8;

    // Stage W slice: Wp[k*2+0] = W[j0..3][k], Wp[k*2+1] = W[j4..7][k]
    for (int idx = tid; idx < HH * 2; idx += 1024) {
        const int k  = idx >> 1;
        const int jh = (idx & 1) * 4;
        float4 v;
        v.x = whh[(size_t)(j0 + jh + 0) * HH + k];
        v.y = whh[(size_t)(j0 + jh + 1) * HH + k];
        v.z = whh[(size_t)(j0 + jh + 2) * HH + k];
        v.w = whh[(size_t)(j0 + jh + 3) * HH + k];
        Wp[idx] = v;
    }

    // ---- t = 0: h_0 = proj[:, 0]
    if (tid < 256) {
        const int n = tid & 31;
        const int j = tid >> 5;
        const float v = __ldg(&proj[((size_t)n * TT) * HH + j0 + j]);
        out[((size_t)n * TT) * HH + j0 + j] = v;
        __stcg(&g_ht[0][(j0 + j) * 32 + n], v);
    }
    grid_barrier(tid);

    // Stage-A roles (all 1024 threads): q = slice-octet, (arj, arn)
    const int q   = tid >> 8;          // 0..3
    const int arj = (tid >> 5) & 7;    // 0..7
    const int arn = tid & 31;          // 0..31
    const int arot = (arn + 4 * arj) & 31;

    // Stage-B roles (first 512 threads): tid<256 -> out, 256..511 -> ht
    const bool bactive  = (tid < 512);
    const bool role_out = (tid < 256);
    const int tid2 = tid & 255;
    const int rn = role_out ? (tid2 >> 3) : (tid2 & 31);
    const int rj = role_out ? (tid2 & 7)  : (tid2 >> 5);
    const int brot = (rn + 4 * rj) & 31;

    const int k0 = w * 32;

    for (int t = 1; t < TT; t++) {
        const float* __restrict__ htp = g_ht[(t - 1) & 1];
        float* __restrict__       htn = g_ht[t & 1];

        // Prefetch proj term (independent of the barrier-protected h).
        float pu = 0.0f;
        if (bactive)
            pu = __ldg(&proj[((size_t)rn * TT + (t - 1)) * HH + j0 + rj]);

        unsigned long long acc01 = 0ull, acc23 = 0ull, acc45 = 0ull, acc67 = 0ull;

        float hb0[8], hb1[8];
#pragma unroll
        for (int i = 0; i < 8; i++)
            hb0[i] = __ldcg(&htp[(k0 + i) * 32 + lane]);

#pragma unroll
        for (int kb = 0; kb < 32; kb += 8) {
            float* cur = ((kb >> 3) & 1) ? hb1 : hb0;
            float* nxt = ((kb >> 3) & 1) ? hb0 : hb1;
            if (kb + 8 < 32) {
#pragma unroll
                for (int i = 0; i < 8; i++)
                    nxt[i] = __ldcg(&htp[(k0 + kb + 8 + i) * 32 + lane]);
            }
#pragma unroll
            for (int i = 0; i < 8; i++) {
                const int k = k0 + kb + i;
                unsigned long long hh2;
                const unsigned hu = __float_as_uint(cur[i]);
                asm("mov.b64 %0, {%1, %1};" : "=l"(hh2) : "r"(hu));
                const ulonglong2 wA = *reinterpret_cast<const ulonglong2*>(&Wp[k * 2 + 0]);
                const ulonglong2 wB = *reinterpret_cast<const ulonglong2*>(&Wp[k * 2 + 1]);
                asm("fma.rn.f32x2 %0, %1, %2, %0;" : "+l"(acc01) : "l"(hh2), "l"(wA.x));
                asm("fma.rn.f32x2 %0, %1, %2, %0;" : "+l"(acc23) : "l"(hh2), "l"(wA.y));
                asm("fma.rn.f32x2 %0, %1, %2, %0;" : "+l"(acc45) : "l"(hh2), "l"(wB.x));
                asm("fma.rn.f32x2 %0, %1, %2, %0;" : "+l"(acc67) : "l"(hh2), "l"(wB.y));
            }
        }

        // Unpack accumulators -> partial, rotated columns (conflict-free).
        {
            unsigned lo, hi;
            asm("mov.b64 {%0,%1}, %2;" : "=r"(lo), "=r"(hi) : "l"(acc01));
            partial[w][0][(lane +  0) & 31] = __uint_as_float(lo);
            partial[w][1][(lane +  4) & 31] = __uint_as_float(hi);
            asm("mov.b64 {%0,%1}, %2;" : "=r"(lo), "=r"(hi) : "l"(acc23));
            partial[w][2][(lane +  8) & 31] = __uint_as_float(lo);
            partial[w][3][(lane + 12) & 31] = __uint_as_float(hi);
            asm("mov.b64 {%0,%1}, %2;" : "=r"(lo), "=r"(hi) : "l"(acc45));
            partial[w][4][(lane + 16) & 31] = __uint_as_float(lo);
            partial[w][5][(lane + 20) & 31] = __uint_as_float(hi);
            asm("mov.b64 {%0,%1}, %2;" : "=r"(lo), "=r"(hi) : "l"(acc67));
            partial[w][6][(lane + 24) & 31] = __uint_as_float(lo);
            partial[w][7][(lane + 28) & 31] = __uint_as_float(hi);
        }
        __syncthreads();

        // Stage A: 32 slices -> 4 (each thread sums its slice-octet).
        {
            float s = partial[q * 8 + 0][arj][arot] + partial[q * 8 + 1][arj][arot]
                    + partial[q * 8 + 2][arj][arot] + partial[q * 8 + 3][arj][arot]
                    + partial[q * 8 + 4][arj][arot] + partial[q * 8 + 5][arj][arot]
                    + partial[q * 8 + 6][arj][arot] + partial[q * 8 + 7][arj][arot];
            partial2[q][arj][arot] = s;
        }
        __syncthreads();

        // Stage B: 4 -> 1, add proj term, store h_t (out + transposed ht).
        if (bactive) {
            const float s = pu
                + partial2[0][rj][brot] + partial2[1][rj][brot]
                + partial2[2][rj][brot] + partial2[3][rj][brot];
            if (role_out) {
                out[((size_t)rn * TT + t) * HH + j0 + rj] = s;   // 32B sectors
            } else {
                __stcg(&htn[(j0 + rj) * 32 + rn], s);            // coalesced
            }
        }

        grid_barrier(tid);
    }
}

// =====================================================================
extern "C" void kernel_launch(void* const* d_in, const int* in_sizes, int n_in,
                              void* d_out, int out_size)
{
    const float* x   = nullptr;
    const float* wih = nullptr;
    const float* bih = nullptr;
    const float* whh = nullptr;
    for (int i = 0; i < n_in; i++) {
        const long s = in_sizes[i];
        if      (s == (long)NB * TT * II) x   = (const float*)d_in[i];
        else if (s == (long)HH * II)      wih = (const float*)d_in[i];
        else if (s == (long)HH)           bih = (const float*)d_in[i];
        else if (s == (long)HH * HH)      whh = (const float*)d_in[i];
    }
    float* out = (float*)d_out;
    const size_t NTH = (size_t)NB * TT * HH;
    float* proj = out + NTH;    // second tuple slot doubles as proj scratch

    dim3 gridA(HH / 64, (NB * TT) / 128);
    proj_gemm<<<gridA, 256>>>(x, wih, bih, proj);

    recurrence<<<RBLOCKS, 1024>>>(whh, proj, out);

    // Overwrite proj scratch with the duplicate output (tuple (out, out)).
    cudaMemcpyAsync(proj, out, NTH * sizeof(float),
                    cudaMemcpyDeviceToDevice, 0);
}

// round 17
// speedup vs baseline: 1.6835x; 1.6835x over previous
#include <cuda_runtime.h>
#include <cstdint>

#define NB 32
#define TT 2048
#define II 512
#define HH 1024

// =====================================================================
// Phase 1: proj = x @ w_ih^T + b_ih  -> second half of d_out (scratch).
// =====================================================================
__global__ __launch_bounds__(256) void proj_gemm(
    const float* __restrict__ x,
    const float* __restrict__ wih,
    const float* __restrict__ bih,
    float* __restrict__ proj)
{
    __shared__ float As[16][132];
    __shared__ float Bs[16][68];

    const int tid = threadIdx.x;
    const int n0 = blockIdx.x * 64;
    const int m0 = blockIdx.y * 128;

    const int ar = tid >> 2;
    const int ac = (tid & 3) << 2;
    const int ty = tid >> 4;
    const int tx = tid & 15;

    float acc[8][4];
#pragma unroll
    for (int i = 0; i < 8; i++)
#pragma unroll
        for (int j = 0; j < 4; j++) acc[i][j] = 0.0f;

    for (int kk = 0; kk < II / 16; kk++) {
        const int k0 = kk * 16;
        const float4 a0 = *reinterpret_cast<const float4*>(
            &x[(size_t)(m0 + ar) * II + k0 + ac]);
        const float4 a1 = *reinterpret_cast<const float4*>(
            &x[(size_t)(m0 + 64 + ar) * II + k0 + ac]);
        const float4 b0 = *reinterpret_cast<const float4*>(
            &wih[(size_t)(n0 + ar) * II + k0 + ac]);

        __syncthreads();
        As[ac + 0][ar] = a0.x;  As[ac + 1][ar] = a0.y;
        As[ac + 2][ar] = a0.z;  As[ac + 3][ar] = a0.w;
        As[ac + 0][64 + ar] = a1.x;  As[ac + 1][64 + ar] = a1.y;
        As[ac + 2][64 + ar] = a1.z;  As[ac + 3][64 + ar] = a1.w;
        Bs[ac + 0][ar] = b0.x;  Bs[ac + 1][ar] = b0.y;
        Bs[ac + 2][ar] = b0.z;  Bs[ac + 3][ar] = b0.w;
        __syncthreads();

#pragma unroll
        for (int k = 0; k < 16; k++) {
            const float4 av0 = *reinterpret_cast<const float4*>(&As[k][ty * 8]);
            const float4 av1 = *reinterpret_cast<const float4*>(&As[k][ty * 8 + 4]);
            const float4 bv  = *reinterpret_cast<const float4*>(&Bs[k][tx * 4]);
            float a[8] = {av0.x, av0.y, av0.z, av0.w, av1.x, av1.y, av1.z, av1.w};
            float b[4] = {bv.x, bv.y, bv.z, bv.w};
#pragma unroll
            for (int i = 0; i < 8; i++)
#pragma unroll
                for (int j = 0; j < 4; j++)
                    acc[i][j] += a[i] * b[j];
        }
    }

    const float4 bias = *reinterpret_cast<const float4*>(&bih[n0 + tx * 4]);
#pragma unroll
    for (int r = 0; r < 8; r++) {
        const int m = m0 + ty * 8 + r;
        float4 o;
        o.x = acc[r][0] + bias.x;
        o.y = acc[r][1] + bias.y;
        o.z = acc[r][2] + bias.z;
        o.w = acc[r][3] + bias.w;
        *reinterpret_cast<float4*>(&proj[(size_t)m * HH + n0 + tx * 4]) = o;
    }
}

// =====================================================================
// Phase 2: persistent recurrence.  h_t = h_{t-1} @ W^T + proj[:, t-1]
// 512 threads, 16 warps; warp w owns 32 k-PAIRS (64 k); lane = n.
// h scratch is PAIR-PACKED: ht2[p][n] = (h_{2p}, h_{2p+1}) as b64 ->
// one LDG.64 is a ready FFMA2 operand (no packing movs, half the LDGs).
// W smem is k-interleaved: Wp2[p][j] = (W[j][2p], W[j][2p+1]).
// Accumulator acc_j = (sum over even k, sum over odd k); lo+hi at end.
// Grid barrier: R11's PROVEN atomic+volatile-phase barrier (the R13/R14
// flag barrier deadlocked twice -> abandoned).
// smem: Wp2 32KB + partial 16KB = 48KB (1 CTA/SM).
// =====================================================================
#define RBLOCKS 128

__device__ unsigned long long g_ht[2][(HH / 2) * 32];   // 2x128KB pair-packed h
__device__ unsigned g_count = 0;
__device__ unsigned g_phase = 0;

__device__ __forceinline__ void grid_barrier(int tid)
{
    __syncthreads();
    if (tid == 0) {
        volatile unsigned* vphase = &g_phase;
        const unsigned my = *vphase;      // read BEFORE arriving
        __threadfence();                  // publish h stores (L2)
        const unsigned arrived = atomicAdd(&g_count, 1u);
        if (arrived == RBLOCKS - 1) {
            g_count = 0;
            __threadfence();
            *vphase = my + 1;             // release
        } else {
            while (*vphase == my) { }
        }
        __threadfence();                  // acquire
    }
    __syncthreads();
}

__global__ __launch_bounds__(512) void recurrence(
    const float* __restrict__ whh,
    const float* __restrict__ proj,
    float* __restrict__ out)
{
    __shared__ __align__(16) unsigned long long Wp2[(HH / 2) * 8];  // 32 KB
    __shared__ float partial[16][8][32];                            // 16 KB

    const int tid  = threadIdx.x;
    const int w    = tid >> 5;     // warp 0..15 -> 32 k-pairs
    const int lane = tid & 31;     // lane = n
    const int j0   = blockIdx.x * 8;

    // Stage W: Wp2[p*8 + j] = (W[j0+j][2p], W[j0+j][2p+1])
    for (int idx = tid; idx < (HH / 2) * 8; idx += 512) {
        const int p = idx >> 3;
        const int j = idx & 7;
        const float2 wv = *reinterpret_cast<const float2*>(
            &whh[(size_t)(j0 + j) * HH + 2 * p]);
        reinterpret_cast<float2&>(Wp2[idx]) = wv;
    }

    // ---- t = 0: h_0 = proj[:, 0]
    if (tid < 256) {
        const int n = tid & 31;
        const int j = tid >> 5;          // 0..7
        const int k = j0 + j;
        const float v = __ldg(&proj[((size_t)n * TT) * HH + k]);
        out[((size_t)n * TT) * HH + k] = v;
        float* htf = reinterpret_cast<float*>(g_ht[0]);
        __stcg(&htf[(size_t)(k >> 1) * 64 + n * 2 + (k & 1)], v);
    }
    grid_barrier(tid);

    // Reduce-phase roles: tid<256 -> store out (n=tid>>3, j=tid&7),
    //                     tid>=256 -> store pair-packed ht (n=tid&31, j=tid>>5)
    const bool role_out = (tid < 256);
    const int tid2 = tid & 255;
    const int rn = role_out ? (tid2 >> 3) : (tid2 & 31);
    const int rj = role_out ? (tid2 & 7)  : (tid2 >> 5);
    const int rot = (rn + 4 * rj) & 31;
    const int rk = j0 + rj;
    const size_t htw_idx = (size_t)(rk >> 1) * 64 + rn * 2 + (rk & 1);

    const int p0 = w * 32;   // first k-pair of this warp

    for (int t = 1; t < TT; t++) {
        const unsigned long long* __restrict__ htp = g_ht[(t - 1) & 1];
        float* __restrict__ htnf = reinterpret_cast<float*>(g_ht[t & 1]);

        // Prefetch proj term (independent of barrier-protected h).
        const float pu = __ldg(&proj[((size_t)rn * TT + (t - 1)) * HH + j0 + rj]);

        unsigned long long acc[8];
#pragma unroll
        for (int j = 0; j < 8; j++) acc[j] = 0ull;

        // Chunks of 4 pairs, refilled TWO chunks ahead (~8 LDG.64 in flight).
        unsigned long long hA[4], hB[4];
#pragma unroll
        for (int q = 0; q < 4; q++)
            hA[q] = __ldcg(&htp[(size_t)(p0 + q) * 32 + lane]);
#pragma unroll
        for (int q = 0; q < 4; q++)
            hB[q] = __ldcg(&htp[(size_t)(p0 + 4 + q) * 32 + lane]);

#pragma unroll
        for (int c = 0; c < 8; c++) {
            unsigned long long* cur = (c & 1) ? hB : hA;
#pragma unroll
            for (int q = 0; q < 4; q++) {
                const int p = p0 + c * 4 + q;
                const unsigned long long hv = cur[q];   // (h_2p, h_2p+1)
                const ulonglong2* wr =
                    reinterpret_cast<const ulonglong2*>(&Wp2[(size_t)p * 8]);
                const ulonglong2 w01 = wr[0];
                const ulonglong2 w23 = wr[1];
                const ulonglong2 w45 = wr[2];
                const ulonglong2 w67 = wr[3];
                asm("fma.rn.f32x2 %0, %1, %2, %0;" : "+l"(acc[0]) : "l"(hv), "l"(w01.x));
                asm("fma.rn.f32x2 %0, %1, %2, %0;" : "+l"(acc[1]) : "l"(hv), "l"(w01.y));
                asm("fma.rn.f32x2 %0, %1, %2, %0;" : "+l"(acc[2]) : "l"(hv), "l"(w23.x));
                asm("fma.rn.f32x2 %0, %1, %2, %0;" : "+l"(acc[3]) : "l"(hv), "l"(w23.y));
                asm("fma.rn.f32x2 %0, %1, %2, %0;" : "+l"(acc[4]) : "l"(hv), "l"(w45.x));
                asm("fma.rn.f32x2 %0, %1, %2, %0;" : "+l"(acc[5]) : "l"(hv), "l"(w45.y));
                asm("fma.rn.f32x2 %0, %1, %2, %0;" : "+l"(acc[6]) : "l"(hv), "l"(w67.x));
                asm("fma.rn.f32x2 %0, %1, %2, %0;" : "+l"(acc[7]) : "l"(hv), "l"(w67.y));
                if (c < 6)   // refill this slot with chunk c+2 (WAR, no wait)
                    cur[q] = __ldcg(&htp[(size_t)(p0 + (c + 2) * 4 + q) * 32 + lane]);
            }
        }

        // Combine (even,odd) halves; store to partial, rotated (conflict-free).
#pragma unroll
        for (int j = 0; j < 8; j++) {
            unsigned lo, hi;
            asm("mov.b64 {%0,%1}, %2;" : "=r"(lo), "=r"(hi) : "l"(acc[j]));
            partial[w][j][(lane + 4 * j) & 31] =
                __uint_as_float(lo) + __uint_as_float(hi);
        }
        __syncthreads();

        // Every thread reduces its own (rn, rj): 16 slices + proj term.
        float s = pu;
#pragma unroll
        for (int sl = 0; sl < 16; sl++)
            s += partial[sl][rj][rot];

        if (role_out) {
            out[((size_t)rn * TT + t) * HH + j0 + rj] = s;   // 32B sectors
        } else {
            __stcg(&htnf[htw_idx], s);                       // pair-packed ht
        }

        grid_barrier(tid);
    }
}

// =====================================================================
extern "C" void kernel_launch(void* const* d_in, const int* in_sizes, int n_in,
                              void* d_out, int out_size)
{
    const float* x   = nullptr;
    const float* wih = nullptr;
    const float* bih = nullptr;
    const float* whh = nullptr;
    for (int i = 0; i < n_in; i++) {
        const long s = in_sizes[i];
        if      (s == (long)NB * TT * II) x   = (const float*)d_in[i];
        else if (s == (long)HH * II)      wih = (const float*)d_in[i];
        else if (s == (long)HH)           bih = (const float*)d_in[i];
        else if (s == (long)HH * HH)      whh = (const float*)d_in[i];
    }
    float* out = (float*)d_out;
    const size_t NTH = (size_t)NB * TT * HH;
    float* proj = out + NTH;    // second tuple slot doubles as proj scratch

    dim3 gridA(HH / 64, (NB * TT) / 128);
    proj_gemm<<<gridA, 256>>>(x, wih, bih, proj);

    recurrence<<<RBLOCKS, 512>>>(whh, proj, out);

    // Overwrite proj scratch with the duplicate output (tuple (out, out)).
    cudaMemcpyAsync(proj, out, NTH * sizeof(float),
                    cudaMemcpyDeviceToDevice, 0);
}